// round 13
// baseline (speedup 1.0000x reference)
#include <cuda_runtime.h>
#include <cstdint>
#include <cstddef>

// ============================ problem constants ============================
#define BATCH_N   4096
#define KDIM      512
#define CLS       50000
#define CLSP      50048              // padded to 391*128
#define SCALE_F   30.0f
#define LMAX_F    30.0f
#define COSM_F    0.8775825618903728f
#define SINM_F    0.479425538604203f
#define TH_F     (-0.8775825618903728f)
#define MMV_F     0.23971276930210156f

// ============================ device scratch ===============================
__device__ float g_Xr[BATCH_N * KDIM];   // tf32-rounded, FRAGMENT-MAJOR X
__device__ float g_Wr[CLSP * KDIM];      // tf32-rounded, k-permuted W (padded)
__device__ float g_invx[BATCH_N];
__device__ float g_invw[CLSP];
__device__ int   g_label[BATCH_N];
__device__ float g_rowsum[BATCH_N];      // sum of exp(logit - 30) per row
__device__ float g_tgt[BATCH_N];         // target-class logit per row
__device__ unsigned int g_ctr = 0;       // CTA completion counter

// ============================ helpers ======================================
__device__ __forceinline__ float f2tf32(float f) {
    uint32_t r; asm("cvt.rna.tf32.f32 %0, %1;" : "=r"(r) : "f"(f));
    return __uint_as_float(r);
}

#define MMA_TF32(c, A0, A1, A2, A3, B0, B1) \
    asm volatile("mma.sync.aligned.m16n8k8.row.col.f32.tf32.tf32.f32 " \
        "{%0,%1,%2,%3}, {%4,%5,%6,%7}, {%8,%9}, {%0,%1,%2,%3};" \
        : "+f"((c)[0]), "+f"((c)[1]), "+f"((c)[2]), "+f"((c)[3]) \
        : "r"(__float_as_uint(A0)), "r"(__float_as_uint(A1)), \
          "r"(__float_as_uint(A2)), "r"(__float_as_uint(A3)), \
          "r"(__float_as_uint(B0)), "r"(__float_as_uint(B1)))

#define CP16(dst_u32, src_gptr) \
    asm volatile("cp.async.cg.shared.global [%0], [%1], 16;" \
        :: "r"(dst_u32), "l"(src_gptr) : "memory")
#define CP_COMMIT() asm volatile("cp.async.commit_group;" ::: "memory")
#define CP_WAIT(n)  asm volatile("cp.async.wait_group %0;" :: "n"(n) : "memory")

__device__ __forceinline__ uint32_t smem_u32(const void* p) {
    uint32_t a;
    asm("{ .reg .u64 t; cvta.to.shared.u64 t, %1; cvt.u32.u64 %0, t; }" : "=r"(a) : "l"(p));
    return a;
}

// ============================ GEMM config ==================================
#define BM     128
#define BN     128
#define BK     16
#define NCH    (KDIM / BK)            // 32 chunks = 16 pairs
#define NPAIR  (NCH / 2)              // 16
// A chunk: 2048 floats fragment-major (8KB); B chunk: 128x16 floats (8KB)
#define ACH    2048
#define STAGEF (ACH + BN * 16)        // 4096 floats = 16KB per chunk-stage
#define PAIRF  (2 * STAGEF)           // 8192 floats = 32KB per pair buffer
#define DSMEM_BYTES (2 * PAIRF * 4)   // 65536 B
#define NTHREADS 256                  // 8 warps, each 64x32 output tile

__device__ __forceinline__ float arc_apply(float cosv, bool istgt) {
    float o = cosv;
    if (istgt) {
        float sine = sqrtf(fmaxf(0.0f, 1.0f - cosv * cosv));
        float phi = cosv * COSM_F - sine * SINM_F;
        o = (cosv > TH_F) ? phi : (cosv - MMV_F);
    }
    return o * SCALE_F;
}

// ============================ prep kernel ==================================
// X rows -> fragment-major; W rows -> k-permuted row-major (16-float rows)
__global__ void __launch_bounds__(128) prep_kernel(
    const float* __restrict__ X, const float* __restrict__ W,
    const int* __restrict__ L)
{
    const int b = blockIdx.x;
    const int t = threadIdx.x;

    if (b < BATCH_N) {
        const int row = b;
        const float* src = X + (size_t)row * KDIM;
        float4 v = *(const float4*)(src + t * 4);
        float ss = v.x * v.x + v.y * v.y + v.z * v.z + v.w * v.w;

        float* dst = g_Xr
            + ((size_t)(row >> 7) * 32 + (t >> 2)) * ACH
            + ((((t >> 1) & 1) * 8 + ((row >> 4) & 7)) * 32 + (row & 7) * 4) * 4
            + ((row >> 3) & 1) + 2 * (t & 1);
        dst[0]  = f2tf32(v.x);
        dst[4]  = f2tf32(v.y);
        dst[8]  = f2tf32(v.z);
        dst[12] = f2tf32(v.w);

        #pragma unroll
        for (int o = 16; o; o >>= 1) ss += __shfl_down_sync(0xffffffffu, ss, o);
        __shared__ float ws[4];
        if ((t & 31) == 0) ws[t >> 5] = ss;
        __syncthreads();
        if (t == 0)
            g_invx[row] = 1.0f / fmaxf(sqrtf(ws[0] + ws[1] + ws[2] + ws[3]), 1e-12f);
    } else if (b < BATCH_N + CLSP) {
        const int row = b - BATCH_N;
        const bool valid = (row < CLS);
        float4 v = make_float4(0.f, 0.f, 0.f, 0.f);
        if (valid) v = *(const float4*)(W + (size_t)row * KDIM + t * 4);
        float ss = v.x * v.x + v.y * v.y + v.z * v.z + v.w * v.w;

        float* gdst = g_Wr + (size_t)row * KDIM + (t >> 2) * 16 + (t & 3);
        gdst[0]  = f2tf32(v.x);
        gdst[4]  = f2tf32(v.y);
        gdst[8]  = f2tf32(v.z);
        gdst[12] = f2tf32(v.w);

        #pragma unroll
        for (int o = 16; o; o >>= 1) ss += __shfl_down_sync(0xffffffffu, ss, o);
        __shared__ float ws2[4];
        if ((t & 31) == 0) ws2[t >> 5] = ss;
        __syncthreads();
        if (t == 0) {
            float tot = ws2[0] + ws2[1] + ws2[2] + ws2[3];
            g_invw[row] = valid ? (1.0f / fmaxf(sqrtf(tot), 1e-12f)) : 1.0f;
        }
    } else {
        int nz = 0;
        for (int i = t; i < 2048; i += 128)
            if (L[2 * i + 1] != 0) nz = 1;
        int any = __syncthreads_or(nz);
        const int is64 = any ? 0 : 1;
        for (int i = t; i < BATCH_N; i += 128) {
            g_label[i] = is64 ? L[2 * i] : L[i];
            g_rowsum[i] = 0.0f;
        }
    }
}

// ============================ main GEMM + ArcFace + loss ===================
extern __shared__ float smf[];

// A fragment: one LDS.128 -> 4 consecutive regs, directly MMA-ready.
__device__ __forceinline__ void compute_chunk(
    const float* __restrict__ sb, int awoff, int boff,
    float acc[4][4][4])
{
    const float* Ab = sb + awoff;
    const float* Bb = sb + boff;
    float4 bq0 = *(const float4*)(Bb);
    float4 bq1 = *(const float4*)(Bb + 8  * 16);
    float4 bq2 = *(const float4*)(Bb + 16 * 16);
    float4 bq3 = *(const float4*)(Bb + 24 * 16);
    #pragma unroll
    for (int i = 0; i < 4; ++i) {
        float4 a0 = *(const float4*)(Ab + i * 128);          // k-step 0
        float4 a1 = *(const float4*)(Ab + 1024 + i * 128);   // k-step 1
        MMA_TF32(acc[i][0], a0.x, a0.y, a0.z, a0.w, bq0.x, bq0.y);
        MMA_TF32(acc[i][1], a0.x, a0.y, a0.z, a0.w, bq1.x, bq1.y);
        MMA_TF32(acc[i][2], a0.x, a0.y, a0.z, a0.w, bq2.x, bq2.y);
        MMA_TF32(acc[i][3], a0.x, a0.y, a0.z, a0.w, bq3.x, bq3.y);
        MMA_TF32(acc[i][0], a1.x, a1.y, a1.z, a1.w, bq0.z, bq0.w);
        MMA_TF32(acc[i][1], a1.x, a1.y, a1.z, a1.w, bq1.z, bq1.w);
        MMA_TF32(acc[i][2], a1.x, a1.y, a1.z, a1.w, bq2.z, bq2.w);
        MMA_TF32(acc[i][3], a1.x, a1.y, a1.z, a1.w, bq3.z, bq3.w);
    }
}

__global__ void __launch_bounds__(NTHREADS, 2)
gemm_arcface_kernel(float* __restrict__ out, int do_loss)
{
    const int tid  = threadIdx.x;
    const int lane = tid & 31;
    const int wid  = tid >> 5;          // 0..7
    const int g    = lane >> 2;
    const int tm   = lane & 3;
    const int wm   = wid & 1;           // warp M index (0..1), 64 rows
    const int wn   = wid >> 1;          // warp N index (0..3), 32 cols
    const int rowTile = blockIdx.x;     // 128-row tile index
    const int colBase = blockIdx.y * BN;

    const uint32_t sbase = smem_u32(smf);
    const uint32_t SOB = (uint32_t)(STAGEF * 4);   // stage bytes
    const uint32_t POB = (uint32_t)(PAIRF * 4);    // pair-buffer bytes

    // fragment smem offsets (floats), loop-invariant
    const int awoff = wm * 4 * 128 + lane * 4;     // + i*128 + s*1024
    const int boff  = ACH + (wn * 32 + g) * 16 + 4 * tm;

    // cp.async A: contiguous 8KB chunk; thread copies 16B at tid*4 and 1024+tid*4
    const float* xsA = g_Xr + (size_t)rowTile * 32 * ACH + tid * 4;
    const uint32_t dAa = sbase + (tid * 4) * 4;
    const uint32_t dAb = sbase + (1024 + tid * 4) * 4;
    // cp.async B: rows r0c, r0c+64 of W (k-permuted 16-float rows per chunk)
    const int r0c = tid >> 2, lc = tid & 3;
    const int r1c = r0c + 64;
    const float* ws0 = g_Wr + (size_t)(colBase + r0c) * KDIM + lc * 4;
    const float* ws1 = g_Wr + (size_t)(colBase + r1c) * KDIM + lc * 4;
    const uint32_t dB0 = sbase + (ACH + r0c * 16 + lc * 4) * 4;
    const uint32_t dB1 = sbase + (ACH + r1c * 16 + lc * 4) * 4;

    float acc[4][4][4];
    #pragma unroll
    for (int i = 0; i < 4; ++i)
        #pragma unroll
        for (int j = 0; j < 4; ++j)
            #pragma unroll
            for (int q = 0; q < 4; ++q) acc[i][j][q] = 0.f;

    // prologue: pair 0 (chunks 0,1) into buffer 0
    CP16(dAa, xsA);              CP16(dAb, xsA + 1024);
    CP16(dB0, ws0);              CP16(dB1, ws1);
    CP16(dAa + SOB, xsA + ACH);  CP16(dAb + SOB, xsA + ACH + 1024);
    CP16(dB0 + SOB, ws0 + BK);   CP16(dB1 + SOB, ws1 + BK);
    CP_COMMIT();

    // main loop: 16 pairs; ONE barrier per pair; issue pair p+1 into the
    // other half-buffer, then compute both chunks of pair p barrier-free.
    #pragma unroll 1
    for (int p = 0; p < NPAIR; ++p) {
        CP_WAIT(0);
        __syncthreads();            // publishes pair p; all reads of other half done
        const uint32_t bn = (p & 1) ? 0u : POB;        // buffer for pair p+1
        if (p + 1 < NPAIR) {
            // pair p+1 = chunks 2p+2, 2p+3 (offsets 2*ACH/3*ACH, 2*BK/3*BK)
            CP16(dAa + bn, xsA + 2 * ACH);
            CP16(dAb + bn, xsA + 2 * ACH + 1024);
            CP16(dB0 + bn, ws0 + 2 * BK);
            CP16(dB1 + bn, ws1 + 2 * BK);
            CP16(dAa + bn + SOB, xsA + 3 * ACH);
            CP16(dAb + bn + SOB, xsA + 3 * ACH + 1024);
            CP16(dB0 + bn + SOB, ws0 + 3 * BK);
            CP16(dB1 + bn + SOB, ws1 + 3 * BK);
            CP_COMMIT();
        }
        const float* pb = smf + (p & 1) * PAIRF;
        compute_chunk(pb,          awoff, boff, acc);
        compute_chunk(pb + STAGEF, awoff, boff, acc);
        xsA += 2 * ACH;
        ws0 += 2 * BK;
        ws1 += 2 * BK;
    }

    // ---- epilogue: normalize, ArcFace margin, scale, store, fused LSE ----
    __syncthreads();
    float* rowacc = smf;               // reuse stage smem: 128 floats
    if (tid < BM) rowacc[tid] = 0.f;
    __syncthreads();

    const int wrowb = rowTile * BM + wm * 64;
    const int wcolb = colBase + wn * 32;
    #pragma unroll
    for (int i = 0; i < 4; ++i) {
        const int r0 = wrowb + i * 16 + g;
        const int r1 = r0 + 8;
        const float ix0 = g_invx[r0], ix1 = g_invx[r1];
        const int lab0 = g_label[r0], lab1 = g_label[r1];
        float* o0 = out + (size_t)r0 * CLS;
        float* o1 = out + (size_t)r1 * CLS;
        float es0 = 0.f, es1 = 0.f;
        #pragma unroll
        for (int j = 0; j < 4; ++j) {
            const int cc = wcolb + j * 8 + 2 * tm;
            if (cc < CLS) {   // cc even, CLS even => cc+1 < CLS too
                const float iw0 = g_invw[cc], iw1 = g_invw[cc + 1];
                const bool t00 = (cc == lab0), t01 = (cc + 1 == lab0);
                const bool t10 = (cc == lab1), t11 = (cc + 1 == lab1);
                float2 v0, v1;
                v0.x = arc_apply(acc[i][j][0] * ix0 * iw0, t00);
                v0.y = arc_apply(acc[i][j][1] * ix0 * iw1, t01);
                v1.x = arc_apply(acc[i][j][2] * ix1 * iw0, t10);
                v1.y = arc_apply(acc[i][j][3] * ix1 * iw1, t11);
                *(float2*)(o0 + cc) = v0;
                *(float2*)(o1 + cc) = v1;
                es0 += __expf(v0.x - LMAX_F) + __expf(v0.y - LMAX_F);
                es1 += __expf(v1.x - LMAX_F) + __expf(v1.y - LMAX_F);
                if (t00) g_tgt[r0] = v0.x;
                if (t01) g_tgt[r0] = v0.y;
                if (t10) g_tgt[r1] = v1.x;
                if (t11) g_tgt[r1] = v1.y;
            }
        }
        es0 += __shfl_xor_sync(0xffffffffu, es0, 1);
        es0 += __shfl_xor_sync(0xffffffffu, es0, 2);
        es1 += __shfl_xor_sync(0xffffffffu, es1, 1);
        es1 += __shfl_xor_sync(0xffffffffu, es1, 2);
        if (tm == 0) {
            atomicAdd(&rowacc[wm * 64 + i * 16 + g],     es0);
            atomicAdd(&rowacc[wm * 64 + i * 16 + g + 8], es1);
        }
    }
    __syncthreads();
    if (tid < BM) atomicAdd(&g_rowsum[rowTile * BM + tid], rowacc[tid]);

    // ---- completion-counter: last CTA computes the CE loss ----
    __shared__ unsigned int s_last;
    __syncthreads();
    if (tid == 0) {
        __threadfence();
        unsigned int total = gridDim.x * gridDim.y;
        unsigned int old = atomicAdd(&g_ctr, 1u);
        s_last = (old == total - 1u) ? 1u : 0u;
    }
    __syncthreads();
    if (s_last) {
        if (tid == 0) g_ctr = 0;
        if (do_loss) {
            __threadfence();
            float s = 0.f;
            for (int i = tid; i < BATCH_N; i += NTHREADS)
                s += (LMAX_F + logf(g_rowsum[i])) - g_tgt[i];
            #pragma unroll
            for (int o = 16; o; o >>= 1) s += __shfl_down_sync(0xffffffffu, s, o);
            float* lsm = smf + 256;
            if (lane == 0) lsm[wid] = s;
            __syncthreads();
            if (tid == 0) {
                float t = 0.f;
                #pragma unroll
                for (int w = 0; w < NTHREADS / 32; ++w) t += lsm[w];
                out[(size_t)BATCH_N * CLS] = t * (1.0f / (float)BATCH_N);
            }
        }
    }
}

// ============================ launcher =====================================
extern "C" void kernel_launch(void* const* d_in, const int* in_sizes, int n_in,
                              void* d_out, int out_size) {
    const float* X = nullptr;
    const float* W = nullptr;
    const int*   L = nullptr;
    for (int i = 0; i < n_in; ++i) {
        if (in_sizes[i] == BATCH_N * KDIM)      X = (const float*)d_in[i];
        else if (in_sizes[i] == CLS * KDIM)     W = (const float*)d_in[i];
        else if (in_sizes[i] == BATCH_N)        L = (const int*)d_in[i];
    }
    float* out = (float*)d_out;
    const int do_loss = ((long long)out_size > (long long)BATCH_N * CLS) ? 1 : 0;

    cudaFuncSetAttribute(gemm_arcface_kernel,
                         cudaFuncAttributeMaxDynamicSharedMemorySize, DSMEM_BYTES);

    // exactly 2 launches per call => ncu -s 5 lands on GEMM
    prep_kernel<<<BATCH_N + CLSP + 1, 128>>>(X, W, L);

    dim3 grid(BATCH_N / BM, CLSP / BN);    // x fast-varying: share W tile in L2
    gemm_arcface_kernel<<<grid, NTHREADS, DSMEM_BYTES>>>(out, do_loss);
}

// round 14
// speedup vs baseline: 1.2017x; 1.2017x over previous
#include <cuda_runtime.h>
#include <cstdint>
#include <cstddef>

// ============================ problem constants ============================
#define BATCH_N   4096
#define KDIM      512
#define CLS       50000
#define CLSP      50048              // padded to 391*128
#define SCALE_F   30.0f
#define LMAX_F    30.0f
#define COSM_F    0.8775825618903728f
#define SINM_F    0.479425538604203f
#define TH_F     (-0.8775825618903728f)
#define MMV_F     0.23971276930210156f

// ============================ device scratch ===============================
__device__ float g_Xr[BATCH_N * KDIM];   // tf32-rounded, FRAGMENT-MAJOR X
__device__ float g_Wr[CLSP * KDIM];      // tf32-rounded, k-permuted W (padded)
__device__ float g_invx[BATCH_N];
__device__ float g_invw[CLSP];
__device__ int   g_label[BATCH_N];
__device__ float g_rowsum[BATCH_N];      // sum of exp(logit - 30) per row
__device__ float g_tgt[BATCH_N];         // target-class logit per row
__device__ unsigned int g_ctr = 0;       // CTA completion counter

// ============================ helpers ======================================
__device__ __forceinline__ float f2tf32(float f) {
    uint32_t r; asm("cvt.rna.tf32.f32 %0, %1;" : "=r"(r) : "f"(f));
    return __uint_as_float(r);
}

#define MMA_TF32(c, A0, A1, A2, A3, B0, B1) \
    asm volatile("mma.sync.aligned.m16n8k8.row.col.f32.tf32.tf32.f32 " \
        "{%0,%1,%2,%3}, {%4,%5,%6,%7}, {%8,%9}, {%0,%1,%2,%3};" \
        : "+f"((c)[0]), "+f"((c)[1]), "+f"((c)[2]), "+f"((c)[3]) \
        : "r"(__float_as_uint(A0)), "r"(__float_as_uint(A1)), \
          "r"(__float_as_uint(A2)), "r"(__float_as_uint(A3)), \
          "r"(__float_as_uint(B0)), "r"(__float_as_uint(B1)))

#define CP16(dst_u32, src_gptr) \
    asm volatile("cp.async.cg.shared.global [%0], [%1], 16;" \
        :: "r"(dst_u32), "l"(src_gptr) : "memory")
#define CP_COMMIT() asm volatile("cp.async.commit_group;" ::: "memory")
#define CP_WAIT(n)  asm volatile("cp.async.wait_group %0;" :: "n"(n) : "memory")

__device__ __forceinline__ uint32_t smem_u32(const void* p) {
    uint32_t a;
    asm("{ .reg .u64 t; cvta.to.shared.u64 t, %1; cvt.u32.u64 %0, t; }" : "=r"(a) : "l"(p));
    return a;
}

// ============================ GEMM config ==================================
#define BM     128
#define BN     128
#define BK     16
#define NCH    (KDIM / BK)            // 32 chunks
#define STAGES 6                      // ring of 6 chunk-stages
// A chunk: 2048 floats fragment-major (8KB); B chunk: 128x16 floats (8KB)
#define ACH    2048
#define STAGEF (ACH + BN * 16)        // 4096 floats = 16KB per chunk-stage
#define DSMEM_BYTES (STAGES * STAGEF * 4)   // 98304 B
#define NTHREADS 256                  // 8 warps, each 64x32 output tile

__device__ __forceinline__ float arc_apply(float cosv, bool istgt) {
    float o = cosv;
    if (istgt) {
        float sine = sqrtf(fmaxf(0.0f, 1.0f - cosv * cosv));
        float phi = cosv * COSM_F - sine * SINM_F;
        o = (cosv > TH_F) ? phi : (cosv - MMV_F);
    }
    return o * SCALE_F;
}

// ============================ prep kernel ==================================
// X rows -> fragment-major; W rows -> k-permuted row-major (16-float rows)
__global__ void __launch_bounds__(128) prep_kernel(
    const float* __restrict__ X, const float* __restrict__ W,
    const int* __restrict__ L)
{
    const int b = blockIdx.x;
    const int t = threadIdx.x;

    if (b < BATCH_N) {
        const int row = b;
        const float* src = X + (size_t)row * KDIM;
        float4 v = *(const float4*)(src + t * 4);
        float ss = v.x * v.x + v.y * v.y + v.z * v.z + v.w * v.w;

        float* dst = g_Xr
            + ((size_t)(row >> 7) * 32 + (t >> 2)) * ACH
            + ((((t >> 1) & 1) * 8 + ((row >> 4) & 7)) * 32 + (row & 7) * 4) * 4
            + ((row >> 3) & 1) + 2 * (t & 1);
        dst[0]  = f2tf32(v.x);
        dst[4]  = f2tf32(v.y);
        dst[8]  = f2tf32(v.z);
        dst[12] = f2tf32(v.w);

        #pragma unroll
        for (int o = 16; o; o >>= 1) ss += __shfl_down_sync(0xffffffffu, ss, o);
        __shared__ float ws[4];
        if ((t & 31) == 0) ws[t >> 5] = ss;
        __syncthreads();
        if (t == 0)
            g_invx[row] = 1.0f / fmaxf(sqrtf(ws[0] + ws[1] + ws[2] + ws[3]), 1e-12f);
    } else if (b < BATCH_N + CLSP) {
        const int row = b - BATCH_N;
        const bool valid = (row < CLS);
        float4 v = make_float4(0.f, 0.f, 0.f, 0.f);
        if (valid) v = *(const float4*)(W + (size_t)row * KDIM + t * 4);
        float ss = v.x * v.x + v.y * v.y + v.z * v.z + v.w * v.w;

        float* gdst = g_Wr + (size_t)row * KDIM + (t >> 2) * 16 + (t & 3);
        gdst[0]  = f2tf32(v.x);
        gdst[4]  = f2tf32(v.y);
        gdst[8]  = f2tf32(v.z);
        gdst[12] = f2tf32(v.w);

        #pragma unroll
        for (int o = 16; o; o >>= 1) ss += __shfl_down_sync(0xffffffffu, ss, o);
        __shared__ float ws2[4];
        if ((t & 31) == 0) ws2[t >> 5] = ss;
        __syncthreads();
        if (t == 0) {
            float tot = ws2[0] + ws2[1] + ws2[2] + ws2[3];
            g_invw[row] = valid ? (1.0f / fmaxf(sqrtf(tot), 1e-12f)) : 1.0f;
        }
    } else {
        int nz = 0;
        for (int i = t; i < 2048; i += 128)
            if (L[2 * i + 1] != 0) nz = 1;
        int any = __syncthreads_or(nz);
        const int is64 = any ? 0 : 1;
        for (int i = t; i < BATCH_N; i += 128) {
            g_label[i] = is64 ? L[2 * i] : L[i];
            g_rowsum[i] = 0.0f;
        }
    }
}

// ============================ main GEMM + ArcFace + loss ===================
extern __shared__ float smf[];

// A fragment: one LDS.128 -> 4 consecutive regs, directly MMA-ready.
__device__ __forceinline__ void compute_chunk(
    const float* __restrict__ sb, int awoff, int boff,
    float acc[4][4][4])
{
    const float* Ab = sb + awoff;
    const float* Bb = sb + boff;
    float4 bq0 = *(const float4*)(Bb);
    float4 bq1 = *(const float4*)(Bb + 8  * 16);
    float4 bq2 = *(const float4*)(Bb + 16 * 16);
    float4 bq3 = *(const float4*)(Bb + 24 * 16);
    #pragma unroll
    for (int i = 0; i < 4; ++i) {
        float4 a0 = *(const float4*)(Ab + i * 128);          // k-step 0
        float4 a1 = *(const float4*)(Ab + 1024 + i * 128);   // k-step 1
        MMA_TF32(acc[i][0], a0.x, a0.y, a0.z, a0.w, bq0.x, bq0.y);
        MMA_TF32(acc[i][1], a0.x, a0.y, a0.z, a0.w, bq1.x, bq1.y);
        MMA_TF32(acc[i][2], a0.x, a0.y, a0.z, a0.w, bq2.x, bq2.y);
        MMA_TF32(acc[i][3], a0.x, a0.y, a0.z, a0.w, bq3.x, bq3.y);
        MMA_TF32(acc[i][0], a1.x, a1.y, a1.z, a1.w, bq0.z, bq0.w);
        MMA_TF32(acc[i][1], a1.x, a1.y, a1.z, a1.w, bq1.z, bq1.w);
        MMA_TF32(acc[i][2], a1.x, a1.y, a1.z, a1.w, bq2.z, bq2.w);
        MMA_TF32(acc[i][3], a1.x, a1.y, a1.z, a1.w, bq3.z, bq3.w);
    }
}

__global__ void __launch_bounds__(NTHREADS, 2)
gemm_arcface_kernel(float* __restrict__ out, int do_loss)
{
    const int tid  = threadIdx.x;
    const int lane = tid & 31;
    const int wid  = tid >> 5;          // 0..7
    const int g    = lane >> 2;
    const int tm   = lane & 3;
    const int wm   = wid & 1;           // warp M index (0..1), 64 rows
    const int wn   = wid >> 1;          // warp N index (0..3), 32 cols
    const int rowTile = blockIdx.x;     // 128-row tile index
    const int colBase = blockIdx.y * BN;

    const uint32_t sbase = smem_u32(smf);

    // fragment smem offsets (floats), loop-invariant
    const int awoff = wm * 4 * 128 + lane * 4;     // + i*128 + s*1024
    const int boff  = ACH + (wn * 32 + g) * 16 + 4 * tm;

    // cp.async A: contiguous 8KB chunk; thread copies 16B at tid*4 and 1024+tid*4
    const float* xsA = g_Xr + (size_t)rowTile * 32 * ACH + tid * 4;
    const uint32_t dAa = sbase + (tid * 4) * 4;
    const uint32_t dAb = sbase + (1024 + tid * 4) * 4;
    // cp.async B: rows r0c, r0c+64 of W (k-permuted 16-float rows per chunk)
    const int r0c = tid >> 2, lc = tid & 3;
    const int r1c = r0c + 64;
    const float* ws0 = g_Wr + (size_t)(colBase + r0c) * KDIM + lc * 4;
    const float* ws1 = g_Wr + (size_t)(colBase + r1c) * KDIM + lc * 4;
    const uint32_t dB0 = sbase + (ACH + r0c * 16 + lc * 4) * 4;
    const uint32_t dB1 = sbase + (ACH + r1c * 16 + lc * 4) * 4;

    float acc[4][4][4];
    #pragma unroll
    for (int i = 0; i < 4; ++i)
        #pragma unroll
        for (int j = 0; j < 4; ++j)
            #pragma unroll
            for (int q = 0; q < 4; ++q) acc[i][j][q] = 0.f;

    // prologue: issue chunks 0..3 into stages 0..3 (one group each)
    #pragma unroll
    for (int s = 0; s < 4; ++s) {
        const uint32_t so = (uint32_t)(s * STAGEF * 4);
        CP16(dAa + so, xsA + s * ACH);
        CP16(dAb + so, xsA + s * ACH + 1024);
        CP16(dB0 + so, ws0 + s * BK);
        CP16(dB1 + so, ws1 + s * BK);
        CP_COMMIT();
    }

    // main loop: 5 blocks of 6 chunks (chunks 0..29).
    // Even chunk: wait(2) [chunks c,c+1 complete] + ONE barrier, issue c+4.
    // Odd chunk:  issue c+5's group only — no wait, no barrier.
    #pragma unroll 1
    for (int b = 0; b < 5; ++b) {
        #pragma unroll
        for (int j = 0; j < 6; ++j) {
            if ((j & 1) == 0) {
                CP_WAIT(2);
                __syncthreads();
            }
            if (j < 4 || b < 4) {          // block 4, j=4,5 would target chunk >= 32
                const uint32_t so = (uint32_t)((((j + 4) % STAGES) * STAGEF) * 4);
                const int ko = (j + 4);
                CP16(dAa + so, xsA + ko * ACH);
                CP16(dAb + so, xsA + ko * ACH + 1024);
                CP16(dB0 + so, ws0 + ko * BK);
                CP16(dB1 + so, ws1 + ko * BK);
                CP_COMMIT();
            }
            compute_chunk(smf + j * STAGEF, awoff, boff, acc);
        }
        xsA += 6 * ACH;
        ws0 += 6 * BK;
        ws1 += 6 * BK;
    }
    // tail: chunks 30 (stage 0), 31 (stage 1)
    CP_WAIT(0);
    __syncthreads();
    compute_chunk(smf + 0 * STAGEF, awoff, boff, acc);
    compute_chunk(smf + 1 * STAGEF, awoff, boff, acc);

    // ---- epilogue: normalize, ArcFace margin, scale, store, fused LSE ----
    __syncthreads();
    float* rowacc = smf;               // reuse stage smem: 128 floats
    if (tid < BM) rowacc[tid] = 0.f;
    __syncthreads();

    const int wrowb = rowTile * BM + wm * 64;
    const int wcolb = colBase + wn * 32;
    #pragma unroll
    for (int i = 0; i < 4; ++i) {
        const int r0 = wrowb + i * 16 + g;
        const int r1 = r0 + 8;
        const float ix0 = g_invx[r0], ix1 = g_invx[r1];
        const int lab0 = g_label[r0], lab1 = g_label[r1];
        float* o0 = out + (size_t)r0 * CLS;
        float* o1 = out + (size_t)r1 * CLS;
        float es0 = 0.f, es1 = 0.f;
        #pragma unroll
        for (int j = 0; j < 4; ++j) {
            const int cc = wcolb + j * 8 + 2 * tm;
            if (cc < CLS) {   // cc even, CLS even => cc+1 < CLS too
                const float iw0 = g_invw[cc], iw1 = g_invw[cc + 1];
                const bool t00 = (cc == lab0), t01 = (cc + 1 == lab0);
                const bool t10 = (cc == lab1), t11 = (cc + 1 == lab1);
                float2 v0, v1;
                v0.x = arc_apply(acc[i][j][0] * ix0 * iw0, t00);
                v0.y = arc_apply(acc[i][j][1] * ix0 * iw1, t01);
                v1.x = arc_apply(acc[i][j][2] * ix1 * iw0, t10);
                v1.y = arc_apply(acc[i][j][3] * ix1 * iw1, t11);
                *(float2*)(o0 + cc) = v0;
                *(float2*)(o1 + cc) = v1;
                es0 += __expf(v0.x - LMAX_F) + __expf(v0.y - LMAX_F);
                es1 += __expf(v1.x - LMAX_F) + __expf(v1.y - LMAX_F);
                if (t00) g_tgt[r0] = v0.x;
                if (t01) g_tgt[r0] = v0.y;
                if (t10) g_tgt[r1] = v1.x;
                if (t11) g_tgt[r1] = v1.y;
            }
        }
        es0 += __shfl_xor_sync(0xffffffffu, es0, 1);
        es0 += __shfl_xor_sync(0xffffffffu, es0, 2);
        es1 += __shfl_xor_sync(0xffffffffu, es1, 1);
        es1 += __shfl_xor_sync(0xffffffffu, es1, 2);
        if (tm == 0) {
            atomicAdd(&rowacc[wm * 64 + i * 16 + g],     es0);
            atomicAdd(&rowacc[wm * 64 + i * 16 + g + 8], es1);
        }
    }
    __syncthreads();
    if (tid < BM) atomicAdd(&g_rowsum[rowTile * BM + tid], rowacc[tid]);

    // ---- completion-counter: last CTA computes the CE loss ----
    __shared__ unsigned int s_last;
    __syncthreads();
    if (tid == 0) {
        __threadfence();
        unsigned int total = gridDim.x * gridDim.y;
        unsigned int old = atomicAdd(&g_ctr, 1u);
        s_last = (old == total - 1u) ? 1u : 0u;
    }
    __syncthreads();
    if (s_last) {
        if (tid == 0) g_ctr = 0;
        if (do_loss) {
            __threadfence();
            float s = 0.f;
            for (int i = tid; i < BATCH_N; i += NTHREADS)
                s += (LMAX_F + logf(g_rowsum[i])) - g_tgt[i];
            #pragma unroll
            for (int o = 16; o; o >>= 1) s += __shfl_down_sync(0xffffffffu, s, o);
            float* lsm = smf + 256;
            if (lane == 0) lsm[wid] = s;
            __syncthreads();
            if (tid == 0) {
                float t = 0.f;
                #pragma unroll
                for (int w = 0; w < NTHREADS / 32; ++w) t += lsm[w];
                out[(size_t)BATCH_N * CLS] = t * (1.0f / (float)BATCH_N);
            }
        }
    }
}

// ============================ launcher =====================================
extern "C" void kernel_launch(void* const* d_in, const int* in_sizes, int n_in,
                              void* d_out, int out_size) {
    const float* X = nullptr;
    const float* W = nullptr;
    const int*   L = nullptr;
    for (int i = 0; i < n_in; ++i) {
        if (in_sizes[i] == BATCH_N * KDIM)      X = (const float*)d_in[i];
        else if (in_sizes[i] == CLS * KDIM)     W = (const float*)d_in[i];
        else if (in_sizes[i] == BATCH_N)        L = (const int*)d_in[i];
    }
    float* out = (float*)d_out;
    const int do_loss = ((long long)out_size > (long long)BATCH_N * CLS) ? 1 : 0;

    cudaFuncSetAttribute(gemm_arcface_kernel,
                         cudaFuncAttributeMaxDynamicSharedMemorySize, DSMEM_BYTES);

    // exactly 2 launches per call => ncu -s 5 lands on GEMM
    prep_kernel<<<BATCH_N + CLSP + 1, 128>>>(X, W, L);

    dim3 grid(BATCH_N / BM, CLSP / BN);    // x fast-varying: share W tile in L2
    gemm_arcface_kernel<<<grid, NTHREADS, DSMEM_BYTES>>>(out, do_loss);
}